// round 11
// baseline (speedup 1.0000x reference)
#include <cuda_runtime.h>

#define B_   16
#define L_   480000
#define D_   9
#define NP1  30000     // level-1 (16-sample rows)
#define NQ2  1875      // level-2
#define NU3  118       // level-3 (1875 padded to 1888)
#define NV4  8         // level-4 (118 padded to 128)
#define RPB  128
#define NBX  235       // ceil(30000/128)

__device__ float g_e1[B_ * D_ * NP1];
__device__ float g_S2[B_ * D_ * NQ2];

// rad = fl( fl(f*h) * fl(1/24000) )  [XLA algsimp HandleDivide: A/c -> A*(1/c)]
#define RECIP_SR ((float)(1.0 / 24000.0))
__device__ __forceinline__ float rad_of(float f, float hd) {
    return __fmul_rn(__fmul_rn(f, hd), RECIP_SR);
}

__device__ __forceinline__ void load16(const float4* p, float x[16]) {
#pragma unroll
    for (int i = 0; i < 4; i++) {
        float4 v = p[i];
        x[4*i] = v.x; x[4*i+1] = v.y; x[4*i+2] = v.z; x[4*i+3] = v.w;
    }
}

// ---- kA: e1[p] = Seq16 of rads (rand_ini folded into element 0) ----
__global__ void __launch_bounds__(256) kA(const float* __restrict__ f0,
                                          const float* __restrict__ rnd) {
    int tid = blockIdx.x * 256 + threadIdx.x;
    if (tid >= B_ * NP1) return;
    int b = tid / NP1, p = tid - b * NP1;
    float f[16];
    load16((const float4*)(f0 + (size_t)b * L_ + (size_t)p * 16), f);
#pragma unroll
    for (int d = 0; d < D_; d++) {
        float hd = (float)(d + 1);
        float acc = 0.f;
#pragma unroll
        for (int j = 0; j < 16; j++) {
            float rad = rad_of(f[j], hd);
            if (p == 0 && j == 0) rad = __fadd_rn(rad, rnd[b * D_ + d]);
            acc = j ? __fadd_rn(acc, rad) : rad;
        }
        g_e1[(size_t)(b * D_ + d) * NP1 + p] = acc;
    }
}

// ---- kB: per (b,d) row -> S2 via e2,e3,e4,S4,S3 (all sequential) ----
__global__ void __launch_bounds__(256) kB() {
    __shared__ float e2[NQ2], e3[NU3], S3[NU3], S4[NV4];
    int row = blockIdx.x, t = threadIdx.x;
    const float* e1 = g_e1 + (size_t)row * NP1;
    for (int q = t; q < NQ2; q += 256) {
        float acc = 0.f;
        for (int j = 0; j < 16; j++) {
            float v = e1[q * 16 + j];
            acc = j ? __fadd_rn(acc, v) : v;
        }
        e2[q] = acc;
    }
    __syncthreads();
    for (int u = t; u < NU3; u += 256) {
        int n = min(16, NQ2 - u * 16);
        float acc = 0.f;
        for (int j = 0; j < n; j++) {
            float v = e2[u * 16 + j];
            acc = j ? __fadd_rn(acc, v) : v;
        }
        e3[u] = acc;
    }
    __syncthreads();
    if (t == 0) {
        float e4[NV4];
        for (int v = 0; v < NV4; v++) {
            int n = min(16, NU3 - v * 16);
            float acc = 0.f;
            for (int j = 0; j < n; j++) {
                float x = e3[v * 16 + j];
                acc = j ? __fadd_rn(acc, x) : x;
            }
            e4[v] = acc;
        }
        float s = 0.f;
        for (int v = 0; v < NV4; v++) {
            s = v ? __fadd_rn(s, e4[v]) : e4[v];
            S4[v] = s;
        }
    }
    __syncthreads();
    for (int u = t; u < NU3; u += 256) {
        int base = (u >> 4) * 16;
        float off = (u >= 16) ? S4[(u >> 4) - 1] : 0.f;
        float acc = 0.f;
        for (int j = base; j <= u; j++)
            acc = (j == base) ? e3[j] : __fadd_rn(acc, e3[j]);
        S3[u] = __fadd_rn(off, acc);
    }
    __syncthreads();
    float* S2 = g_S2 + (size_t)row * NQ2;
    for (int q = t; q < NQ2; q += 256) {
        int base = (q >> 4) * 16;
        float off = (q >= 16) ? S3[(q >> 4) - 1] : 0.f;
        float acc = 0.f;
        for (int j = base; j <= q; j++)
            acc = (j == base) ? e2[j] : __fadd_rn(acc, e2[j]);
        S2[q] = __fadd_rn(off, acc);
    }
}

__device__ __forceinline__ float sin_ph(float ph) {
    float k = rintf(__fmul_rn(ph, 0.15915494309189535f));
    float r = __fmaf_rn(k, -6.28318548202514648f, ph);
    r       = __fmaf_rn(k, 1.7484556e-07f, r);
    return __sinf(r);
}

// ---- kC: S1 from (S2, e1); out[m] = S1[r-1] + Seq16(rad); sin; staged store ----
__global__ void __launch_bounds__(128) kC(const float* __restrict__ f0,
                                          const float* __restrict__ rnd,
                                          float* __restrict__ outS,
                                          float* __restrict__ outU, int writeU) {
    extern __shared__ float sm[];
    float* se1   = sm;              // [9][144]
    float* sS1   = sm + 1296;       // [9][144]
    float* sS2   = sm + 2592;       // [9][9]
    float* stage = sm + 2688;       // [128*145]
    int b  = blockIdx.y;
    int r0 = blockIdx.x * RPB;
    int nrows = min(RPB, NP1 - r0);
    int q0 = r0 >> 4;
    int t = threadIdx.x;

    for (int i = t; i < 9 * 144; i += 128) {
        int d = i / 144, k = i - d * 144;
        int q = q0 - 1 + (k >> 4);
        int p = q * 16 + (k & 15);
        se1[i] = (q >= 0 && p < NP1) ? g_e1[(size_t)(b * D_ + d) * NP1 + p] : 0.f;
    }
    for (int i = t; i < 81; i += 128) {
        int d = i / 9, qq = i - d * 9;
        int qm = q0 - 2 + qq;
        sS2[i] = (qm >= 0 && qm < NQ2) ? g_S2[(size_t)(b * D_ + d) * NQ2 + qm] : 0.f;
    }
    __syncthreads();
    if (t < 81) {
        int d = t / 9, qq = t - d * 9;
        int q = q0 - 1 + qq;
        if (q >= 0) {
            float off = sS2[d * 9 + qq];
            float acc = 0.f;
            for (int j = 0; j < 16; j++) {
                int p = q * 16 + j;
                if (p < NP1) {
                    float v = se1[d * 144 + qq * 16 + j];
                    acc = j ? __fadd_rn(acc, v) : v;
                    sS1[d * 144 + qq * 16 + j] = __fadd_rn(off, acc);
                }
            }
        }
    }
    __syncthreads();

    if (t < nrows) {
        int r = r0 + t;
        float f[16];
        load16((const float4*)(f0 + (size_t)b * L_ + (size_t)r * 16), f);
        if (writeU) {
            float4* up = (float4*)(outU + (size_t)b * L_ + (size_t)r * 16);
#pragma unroll
            for (int i = 0; i < 4; i++)
                up[i] = make_float4(f[4*i] > 0.f ? 1.f : 0.f, f[4*i+1] > 0.f ? 1.f : 0.f,
                                    f[4*i+2] > 0.f ? 1.f : 0.f, f[4*i+3] > 0.f ? 1.f : 0.f);
        }
#pragma unroll
        for (int d = 0; d < D_; d++) {
            float off0 = 0.f;
            if (r > 0) {
                int k = (r - 1) - (q0 - 1) * 16;
                off0 = sS1[d * 144 + k];
            }
            float hd = (float)(d + 1);
            float acc = 0.f;
#pragma unroll
            for (int j = 0; j < 16; j++) {
                float rad = rad_of(f[j], hd);
                if (r == 0 && j == 0) rad = __fadd_rn(rad, rnd[b * D_ + d]);
                acc = j ? __fadd_rn(acc, rad) : rad;
                float s  = __fadd_rn(off0, acc);
                float ph = __fmul_rn(s, 6.28318548202514648f);
                float sv = sin_ph(ph);
                float ov = (f[j] > 0.f) ? __fmul_rn(sv, 0.1f) : 0.f;
                stage[t * 145 + j * 9 + d] = ov;
            }
        }
    }
    __syncthreads();
    int totw4 = nrows * 36;
    float4* og = (float4*)(outS + ((size_t)b * L_ + (size_t)r0 * 16) * D_);
    for (int w4 = t; w4 < totw4; w4 += 128) {
        int w = w4 << 2;
        int tr = w / 144, off = w - tr * 144;
        const float* s = stage + tr * 145 + off;
        og[w4] = make_float4(s[0], s[1], s[2], s[3]);
    }
}

#define SMEM_KC ((2688 + 128 * 145) * 4)

extern "C" void kernel_launch(void* const* d_in, const int* in_sizes, int n_in,
                              void* d_out, int out_size) {
    const float* f0  = (const float*)d_in[0];
    const float* rnd = (const float*)d_in[1];
    float* outS = (float*)d_out;
    float* outU = outS + (size_t)B_ * L_ * D_;
    int writeU = (out_size >= B_ * L_ * D_ + B_ * L_) ? 1 : 0;

    static int init = 0;
    if (!init) {
        cudaFuncSetAttribute(kC, cudaFuncAttributeMaxDynamicSharedMemorySize, SMEM_KC);
        init = 1;
    }

    kA<<<(B_ * NP1 + 255) / 256, 256>>>(f0, rnd);
    kB<<<B_ * D_, 256>>>();
    dim3 gc(NBX, B_);
    kC<<<gc, 128, SMEM_KC>>>(f0, rnd, outS, outU, writeU);
}

// round 12
// speedup vs baseline: 1.4055x; 1.4055x over previous
#include <cuda_runtime.h>

#define B_   16
#define L_   480000
#define D_   9
#define NP1  30000     // level-1 (16-sample rows)
#define NQ2  1875      // level-2
#define NU3  118       // level-3 (1875 padded to 1888)
#define NV4  8         // level-4 (118 padded to 128)
#define RPB  128
#define NBX  235       // ceil(30000/128)

__device__ float g_e1[B_ * D_ * NP1];
__device__ float g_S2[B_ * D_ * NQ2];

// rad = fl( fl(f*h) * fl(1/24000) )  [XLA algsimp HandleDivide: A/c -> A*(1/c)]
#define RECIP_SR ((float)(1.0 / 24000.0))
__device__ __forceinline__ float rad_of(float f, float hd) {
    return __fmul_rn(__fmul_rn(f, hd), RECIP_SR);
}

__device__ __forceinline__ void load16(const float4* p, float x[16]) {
#pragma unroll
    for (int i = 0; i < 4; i++) {
        float4 v = p[i];
        x[4*i] = v.x; x[4*i+1] = v.y; x[4*i+2] = v.z; x[4*i+3] = v.w;
    }
}

// ---- kA: e1[p] = Seq16 of rads (rand_ini folded into element 0) ----
__global__ void __launch_bounds__(256) kA(const float* __restrict__ f0,
                                          const float* __restrict__ rnd) {
    int tid = blockIdx.x * 256 + threadIdx.x;
    if (tid >= B_ * NP1) return;
    int b = tid / NP1, p = tid - b * NP1;
    float f[16];
    load16((const float4*)(f0 + (size_t)b * L_ + (size_t)p * 16), f);
#pragma unroll
    for (int d = 0; d < D_; d++) {
        float hd = (float)(d + 1);
        float acc = 0.f;
#pragma unroll
        for (int j = 0; j < 16; j++) {
            float rad = rad_of(f[j], hd);
            if (p == 0 && j == 0) rad = __fadd_rn(rad, rnd[b * D_ + d]);
            acc = j ? __fadd_rn(acc, rad) : rad;
        }
        g_e1[(size_t)(b * D_ + d) * NP1 + p] = acc;
    }
}

// ---- kB: per (b,d) row -> S2 via e2,e3,e4,S4,S3 (all sequential) ----
__global__ void __launch_bounds__(512) kB() {
    __shared__ float e2[NQ2], e3[NU3], S3[NU3], S4[NV4];
    int row = blockIdx.x, t = threadIdx.x;
    const float* e1 = g_e1 + (size_t)row * NP1;
    for (int q = t; q < NQ2; q += 512) {
        float x[16];
        load16((const float4*)(e1 + q * 16), x);
        float acc = x[0];
#pragma unroll
        for (int j = 1; j < 16; j++) acc = __fadd_rn(acc, x[j]);
        e2[q] = acc;
    }
    __syncthreads();
    for (int u = t; u < NU3; u += 512) {
        int n = min(16, NQ2 - u * 16);
        float acc = 0.f;
        for (int j = 0; j < n; j++) {
            float v = e2[u * 16 + j];
            acc = j ? __fadd_rn(acc, v) : v;
        }
        e3[u] = acc;
    }
    __syncthreads();
    if (t == 0) {
        float e4[NV4];
        for (int v = 0; v < NV4; v++) {
            int n = min(16, NU3 - v * 16);
            float acc = 0.f;
            for (int j = 0; j < n; j++) {
                float x = e3[v * 16 + j];
                acc = j ? __fadd_rn(acc, x) : x;
            }
            e4[v] = acc;
        }
        float s = 0.f;
        for (int v = 0; v < NV4; v++) {
            s = v ? __fadd_rn(s, e4[v]) : e4[v];
            S4[v] = s;
        }
    }
    __syncthreads();
    for (int u = t; u < NU3; u += 512) {
        int base = (u >> 4) * 16;
        float off = (u >= 16) ? S4[(u >> 4) - 1] : 0.f;
        float acc = 0.f;
        for (int j = base; j <= u; j++)
            acc = (j == base) ? e3[j] : __fadd_rn(acc, e3[j]);
        S3[u] = __fadd_rn(off, acc);
    }
    __syncthreads();
    float* S2 = g_S2 + (size_t)row * NQ2;
    for (int q = t; q < NQ2; q += 512) {
        int base = (q >> 4) * 16;
        float off = (q >= 16) ? S3[(q >> 4) - 1] : 0.f;
        float acc = 0.f;
        for (int j = base; j <= q; j++)
            acc = (j == base) ? e2[j] : __fadd_rn(acc, e2[j]);
        S2[q] = __fadd_rn(off, acc);
    }
}

__device__ __forceinline__ float sin_ph(float ph) {
    float k = rintf(__fmul_rn(ph, 0.15915494309189535f));
    float r = __fmaf_rn(k, -6.28318548202514648f, ph);
    r       = __fmaf_rn(k, 1.7484556e-07f, r);
    return __sinf(r);
}

// ---- kC: 256 threads, 2 threads/row (split 8+8 with recomputed prefix) ----
__global__ void __launch_bounds__(256) kC(const float* __restrict__ f0,
                                          const float* __restrict__ rnd,
                                          float* __restrict__ outS,
                                          float* __restrict__ outU, int writeU) {
    extern __shared__ float sm[];
    float* se1   = sm;              // [9][144]
    float* sS1   = sm + 1296;       // [9][144]
    float* sS2   = sm + 2592;       // [9][9]
    float* stage = sm + 2688;       // [128*145]
    int b  = blockIdx.y;
    int r0 = blockIdx.x * RPB;
    int nrows = min(RPB, NP1 - r0);
    int q0 = r0 >> 4;
    int t = threadIdx.x;

    for (int i = t; i < 9 * 144; i += 256) {
        int d = i / 144, k = i - d * 144;
        int q = q0 - 1 + (k >> 4);
        int p = q * 16 + (k & 15);
        se1[i] = (q >= 0 && p < NP1) ? g_e1[(size_t)(b * D_ + d) * NP1 + p] : 0.f;
    }
    for (int i = t; i < 81; i += 256) {
        int d = i / 9, qq = i - d * 9;
        int qm = q0 - 2 + qq;
        sS2[i] = (qm >= 0 && qm < NQ2) ? g_S2[(size_t)(b * D_ + d) * NQ2 + qm] : 0.f;
    }
    __syncthreads();
    if (t < 81) {
        int d = t / 9, qq = t - d * 9;
        int q = q0 - 1 + qq;
        if (q >= 0) {
            float off = sS2[d * 9 + qq];
            float acc = 0.f;
            for (int j = 0; j < 16; j++) {
                int p = q * 16 + j;
                if (p < NP1) {
                    float v = se1[d * 144 + qq * 16 + j];
                    acc = j ? __fadd_rn(acc, v) : v;
                    sS1[d * 144 + qq * 16 + j] = __fadd_rn(off, acc);
                }
            }
        }
    }
    __syncthreads();

    int half = t >> 7, tr = t & 127;
    if (tr < nrows) {
        int r = r0 + tr;
        float f[16];
        load16((const float4*)(f0 + (size_t)b * L_ + (size_t)r * 16), f);
        if (writeU) {
            float4* up = (float4*)(outU + (size_t)b * L_ + (size_t)r * 16);
            if (half == 0) {
                up[0] = make_float4(f[0]>0.f?1.f:0.f, f[1]>0.f?1.f:0.f,
                                    f[2]>0.f?1.f:0.f, f[3]>0.f?1.f:0.f);
                up[1] = make_float4(f[4]>0.f?1.f:0.f, f[5]>0.f?1.f:0.f,
                                    f[6]>0.f?1.f:0.f, f[7]>0.f?1.f:0.f);
            } else {
                up[2] = make_float4(f[8]>0.f?1.f:0.f,  f[9]>0.f?1.f:0.f,
                                    f[10]>0.f?1.f:0.f, f[11]>0.f?1.f:0.f);
                up[3] = make_float4(f[12]>0.f?1.f:0.f, f[13]>0.f?1.f:0.f,
                                    f[14]>0.f?1.f:0.f, f[15]>0.f?1.f:0.f);
            }
        }
#pragma unroll
        for (int d = 0; d < D_; d++) {
            float off0 = 0.f;
            if (r > 0) {
                int k = (r - 1) - (q0 - 1) * 16;
                off0 = sS1[d * 144 + k];
            }
            float hd = (float)(d + 1);
            float acc = 0.f;
            if (half == 0) {
#pragma unroll
                for (int j = 0; j < 8; j++) {
                    float rad = rad_of(f[j], hd);
                    if (r == 0 && j == 0) rad = __fadd_rn(rad, rnd[b * D_ + d]);
                    acc = j ? __fadd_rn(acc, rad) : rad;
                    float s  = __fadd_rn(off0, acc);
                    float ph = __fmul_rn(s, 6.28318548202514648f);
                    float sv = sin_ph(ph);
                    float ov = (f[j] > 0.f) ? __fmul_rn(sv, 0.1f) : 0.f;
                    stage[tr * 145 + j * 9 + d] = ov;
                }
            } else {
#pragma unroll
                for (int j = 0; j < 8; j++) {      // recompute prefix fold (exact)
                    float rad = rad_of(f[j], hd);
                    if (r == 0 && j == 0) rad = __fadd_rn(rad, rnd[b * D_ + d]);
                    acc = j ? __fadd_rn(acc, rad) : rad;
                }
#pragma unroll
                for (int j = 8; j < 16; j++) {
                    float rad = rad_of(f[j], hd);
                    acc = __fadd_rn(acc, rad);
                    float s  = __fadd_rn(off0, acc);
                    float ph = __fmul_rn(s, 6.28318548202514648f);
                    float sv = sin_ph(ph);
                    float ov = (f[j] > 0.f) ? __fmul_rn(sv, 0.1f) : 0.f;
                    stage[tr * 145 + j * 9 + d] = ov;
                }
            }
        }
    }
    __syncthreads();
    int totw4 = nrows * 36;
    float4* og = (float4*)(outS + ((size_t)b * L_ + (size_t)r0 * 16) * D_);
    for (int w4 = t; w4 < totw4; w4 += 256) {
        int w = w4 << 2;
        int trr = w / 144, off = w - trr * 144;
        const float* s = stage + trr * 145 + off;
        og[w4] = make_float4(s[0], s[1], s[2], s[3]);
    }
}

#define SMEM_KC ((2688 + 128 * 145) * 4)

extern "C" void kernel_launch(void* const* d_in, const int* in_sizes, int n_in,
                              void* d_out, int out_size) {
    const float* f0  = (const float*)d_in[0];
    const float* rnd = (const float*)d_in[1];
    float* outS = (float*)d_out;
    float* outU = outS + (size_t)B_ * L_ * D_;
    int writeU = (out_size >= B_ * L_ * D_ + B_ * L_) ? 1 : 0;

    static int init = 0;
    if (!init) {
        cudaFuncSetAttribute(kC, cudaFuncAttributeMaxDynamicSharedMemorySize, SMEM_KC);
        init = 1;
    }

    kA<<<(B_ * NP1 + 255) / 256, 256>>>(f0, rnd);
    kB<<<B_ * D_, 512>>>();
    dim3 gc(NBX, B_);
    kC<<<gc, 256, SMEM_KC>>>(f0, rnd, outS, outU, writeU);
}

// round 13
// speedup vs baseline: 1.6977x; 1.2079x over previous
#include <cuda_runtime.h>

#define B_   16
#define L_   480000
#define D_   9
#define NP1  30000     // level-1 (16-sample rows)
#define NQ2  1875      // level-2
#define NU3  118       // level-3 (1875 padded to 1888)
#define NV4  8         // level-4 (118 padded to 128)
#define RPB  64
#define NBX  469       // ceil(30000/64)

__device__ float g_e1[B_ * D_ * NP1];
__device__ float g_S2[B_ * D_ * NQ2];

// rad = fl( fl(f*h) * fl(1/24000) )  [XLA algsimp HandleDivide: A/c -> A*(1/c)]
#define RECIP_SR ((float)(1.0 / 24000.0))
__device__ __forceinline__ float rad_of(float f, float hd) {
    return __fmul_rn(__fmul_rn(f, hd), RECIP_SR);
}

__device__ __forceinline__ void load16(const float4* p, float x[16]) {
#pragma unroll
    for (int i = 0; i < 4; i++) {
        float4 v = p[i];
        x[4*i] = v.x; x[4*i+1] = v.y; x[4*i+2] = v.z; x[4*i+3] = v.w;
    }
}

// ---- kA: e1[p] = Seq16 of rads (rand_ini folded into element 0) ----
__global__ void __launch_bounds__(256) kA(const float* __restrict__ f0,
                                          const float* __restrict__ rnd) {
    int tid = blockIdx.x * 256 + threadIdx.x;
    if (tid >= B_ * NP1) return;
    int b = tid / NP1, p = tid - b * NP1;
    float f[16];
    load16((const float4*)(f0 + (size_t)b * L_ + (size_t)p * 16), f);
#pragma unroll
    for (int d = 0; d < D_; d++) {
        float hd = (float)(d + 1);
        float acc = 0.f;
#pragma unroll
        for (int j = 0; j < 16; j++) {
            float rad = rad_of(f[j], hd);
            if (p == 0 && j == 0) rad = __fadd_rn(rad, rnd[b * D_ + d]);
            acc = j ? __fadd_rn(acc, rad) : rad;
        }
        g_e1[(size_t)(b * D_ + d) * NP1 + p] = acc;
    }
}

// ---- kB: per (b,d) row -> S2 via e2,e3,e4,S4,S3 (all sequential) ----
__global__ void __launch_bounds__(512) kB() {
    __shared__ float e2[NQ2], e3[NU3], S3[NU3], S4[NV4];
    int row = blockIdx.x, t = threadIdx.x;
    const float* e1 = g_e1 + (size_t)row * NP1;
    for (int q = t; q < NQ2; q += 512) {
        float x[16];
        load16((const float4*)(e1 + q * 16), x);
        float acc = x[0];
#pragma unroll
        for (int j = 1; j < 16; j++) acc = __fadd_rn(acc, x[j]);
        e2[q] = acc;
    }
    __syncthreads();
    for (int u = t; u < NU3; u += 512) {
        int n = min(16, NQ2 - u * 16);
        float acc = 0.f;
        for (int j = 0; j < n; j++) {
            float v = e2[u * 16 + j];
            acc = j ? __fadd_rn(acc, v) : v;
        }
        e3[u] = acc;
    }
    __syncthreads();
    if (t == 0) {
        float e4[NV4];
        for (int v = 0; v < NV4; v++) {
            int n = min(16, NU3 - v * 16);
            float acc = 0.f;
            for (int j = 0; j < n; j++) {
                float x = e3[v * 16 + j];
                acc = j ? __fadd_rn(acc, x) : x;
            }
            e4[v] = acc;
        }
        float s = 0.f;
        for (int v = 0; v < NV4; v++) {
            s = v ? __fadd_rn(s, e4[v]) : e4[v];
            S4[v] = s;
        }
    }
    __syncthreads();
    for (int u = t; u < NU3; u += 512) {
        int base = (u >> 4) * 16;
        float off = (u >= 16) ? S4[(u >> 4) - 1] : 0.f;
        float acc = 0.f;
        for (int j = base; j <= u; j++)
            acc = (j == base) ? e3[j] : __fadd_rn(acc, e3[j]);
        S3[u] = __fadd_rn(off, acc);
    }
    __syncthreads();
    float* S2 = g_S2 + (size_t)row * NQ2;
    for (int q = t; q < NQ2; q += 512) {
        int base = (q >> 4) * 16;
        float off = (q >= 16) ? S3[(q >> 4) - 1] : 0.f;
        float acc = 0.f;
        for (int j = base; j <= q; j++)
            acc = (j == base) ? e2[j] : __fadd_rn(acc, e2[j]);
        S2[q] = __fadd_rn(off, acc);
    }
}

__device__ __forceinline__ float sin_ph(float ph) {
    float k = rintf(__fmul_rn(ph, 0.15915494309189535f));
    float r = __fmaf_rn(k, -6.28318548202514648f, ph);
    r       = __fmaf_rn(k, 1.7484556e-07f, r);
    return __sinf(r);
}

// one quarter of a row: recompute exact J0-prefix fold, emit samples J0..J0+3
template<int J0>
__device__ __forceinline__ void row_quarter(
    const float* __restrict__ fptr, const float* __restrict__ rnd9,
    int r, int kidx, const float* __restrict__ sS1,
    float* __restrict__ stageRow, float* __restrict__ upPtr, int writeU)
{
    constexpr int NF = J0 + 4;
    float f[NF];
#pragma unroll
    for (int i = 0; i < NF / 4; i++) {
        float4 v = ((const float4*)fptr)[i];
        f[4*i] = v.x; f[4*i+1] = v.y; f[4*i+2] = v.z; f[4*i+3] = v.w;
    }
    if (writeU) {
        ((float4*)upPtr)[J0 / 4] =
            make_float4(f[J0]>0.f?1.f:0.f, f[J0+1]>0.f?1.f:0.f,
                        f[J0+2]>0.f?1.f:0.f, f[J0+3]>0.f?1.f:0.f);
    }
#pragma unroll
    for (int d = 0; d < D_; d++) {
        float off0 = (r > 0) ? sS1[d * 80 + kidx] : 0.f;
        float hd = (float)(d + 1);
        float acc = 0.f;
#pragma unroll
        for (int j = 0; j < J0; j++) {
            float rad = rad_of(f[j], hd);
            if (r == 0 && j == 0) rad = __fadd_rn(rad, rnd9[d]);
            acc = j ? __fadd_rn(acc, rad) : rad;
        }
#pragma unroll
        for (int j = J0; j < J0 + 4; j++) {
            float rad = rad_of(f[j], hd);
            if (r == 0 && j == 0) rad = __fadd_rn(rad, rnd9[d]);
            acc = j ? __fadd_rn(acc, rad) : rad;
            float s  = __fadd_rn(off0, acc);
            float ph = __fmul_rn(s, 6.28318548202514648f);
            float sv = sin_ph(ph);
            stageRow[j * 9 + d] = (f[j] > 0.f) ? __fmul_rn(sv, 0.1f) : 0.f;
        }
    }
}

// ---- kC: 256 threads, 4 threads/row over 64 rows ----
__global__ void __launch_bounds__(256) kC(const float* __restrict__ f0,
                                          const float* __restrict__ rnd,
                                          float* __restrict__ outS,
                                          float* __restrict__ outU, int writeU) {
    extern __shared__ float sm[];
    float* se1   = sm;              // [9][80]
    float* sS1   = sm + 720;        // [9][80]
    float* sS2   = sm + 1440;       // [9][5]
    float* stage = sm + 1488;       // [64*145]
    int b  = blockIdx.y;
    int r0 = blockIdx.x * RPB;
    int nrows = min(RPB, NP1 - r0);
    int q0 = r0 >> 4;
    int t = threadIdx.x;

    for (int i = t; i < 720; i += 256) {
        int d = i / 80, k = i - d * 80;
        int q = q0 - 1 + (k >> 4);
        int p = q * 16 + (k & 15);
        se1[i] = (q >= 0 && p < NP1) ? g_e1[(size_t)(b * D_ + d) * NP1 + p] : 0.f;
    }
    if (t < 45) {
        int d = t / 5, qq = t - d * 5;
        int qm = q0 - 2 + qq;
        sS2[d * 5 + qq] = (qm >= 0 && qm < NQ2) ? g_S2[(size_t)(b * D_ + d) * NQ2 + qm] : 0.f;
    }
    __syncthreads();
    if (t < 45) {
        int d = t / 5, qq = t - d * 5;
        int q = q0 - 1 + qq;
        if (q >= 0) {
            float off = sS2[d * 5 + qq];
            float acc = 0.f;
            for (int j = 0; j < 16; j++) {
                int p = q * 16 + j;
                if (p < NP1) {
                    float v = se1[d * 80 + qq * 16 + j];
                    acc = j ? __fadd_rn(acc, v) : v;
                    sS1[d * 80 + qq * 16 + j] = __fadd_rn(off, acc);
                }
            }
        }
    }
    __syncthreads();

    int qk = t >> 6, tr = t & 63;
    if (tr < nrows) {
        int r = r0 + tr;
        const float* fptr = f0 + (size_t)b * L_ + (size_t)r * 16;
        float* upPtr = outU + (size_t)b * L_ + (size_t)r * 16;
        const float* rnd9 = rnd + b * D_;
        int kidx = (r - 1) - (q0 - 1) * 16;   // 15..78 when r>0
        float* stageRow = stage + tr * 145;
        switch (qk) {
            case 0: row_quarter<0>(fptr, rnd9, r, kidx, sS1, stageRow, upPtr, writeU); break;
            case 1: row_quarter<4>(fptr, rnd9, r, kidx, sS1, stageRow, upPtr, writeU); break;
            case 2: row_quarter<8>(fptr, rnd9, r, kidx, sS1, stageRow, upPtr, writeU); break;
            default: row_quarter<12>(fptr, rnd9, r, kidx, sS1, stageRow, upPtr, writeU); break;
        }
    }
    __syncthreads();
    int totw4 = nrows * 36;
    float4* og = (float4*)(outS + ((size_t)b * L_ + (size_t)r0 * 16) * D_);
    for (int w4 = t; w4 < totw4; w4 += 256) {
        int w = w4 << 2;
        int trr = w / 144, off = w - trr * 144;
        const float* s = stage + trr * 145 + off;
        og[w4] = make_float4(s[0], s[1], s[2], s[3]);
    }
}

#define SMEM_KC ((1488 + 64 * 145) * 4)

extern "C" void kernel_launch(void* const* d_in, const int* in_sizes, int n_in,
                              void* d_out, int out_size) {
    const float* f0  = (const float*)d_in[0];
    const float* rnd = (const float*)d_in[1];
    float* outS = (float*)d_out;
    float* outU = outS + (size_t)B_ * L_ * D_;
    int writeU = (out_size >= B_ * L_ * D_ + B_ * L_) ? 1 : 0;

    static int init = 0;
    if (!init) {
        cudaFuncSetAttribute(kC, cudaFuncAttributeMaxDynamicSharedMemorySize, SMEM_KC);
        init = 1;
    }

    kA<<<(B_ * NP1 + 255) / 256, 256>>>(f0, rnd);
    kB<<<B_ * D_, 512>>>();
    dim3 gc(NBX, B_);
    kC<<<gc, 256, SMEM_KC>>>(f0, rnd, outS, outU, writeU);
}